// round 15
// baseline (speedup 1.0000x reference)
#include <cuda_runtime.h>
#include <cuda_fp16.h>
#include <math.h>

#define NN 50000
#define EE 500000
#define HH 128
#define NHH 8
// DH = 16, scale = 0.25 (folded into q GEMM)

#define MAXDEG_SMEM 64
#define MLP_SMEM (3 * 128 * 68 * 4)   // As + Bs + Hs, half2[128][68] each

// ---------------- scratch (device globals; no runtime alloc) ----------------
__device__ float g_agg [(size_t)NN * HH];   // z = h+agg -> xl (in-place)
__device__ __half g_qh [(size_t)NN * HH];
__device__ __half g_kh [(size_t)NN * HH];
__device__ __half g_vh [(size_t)NN * HH];
__device__ float g_ao  [(size_t)NN * HH];   // xa
__device__ float g_hc  [(size_t)NN * HH];   // combine -> +FFN (in-place)
__device__ float g_sum  [3][HH];
__device__ float g_sumsq[3][HH];
__device__ float g_bnA  [3][HH];
__device__ float g_bnB  [3][HH];
// CSR scratch
__device__ int  g_cnt_s[NN];
__device__ int  g_cnt_d[NN];
__device__ int  g_fill_s[NN];
__device__ int  g_fill_d[NN];
__device__ int  g_rp_s[NN + 1];
__device__ int  g_rp_d[NN + 1];
__device__ int  g_bsum[2][64];
__device__ int2 g_eps[EE];   // (dst, eid) sorted by src
__device__ int2 g_epd[EE];   // (src, eid) sorted by dst

// ---------------- small helpers ----------------
__device__ __forceinline__ void redf(float* p, float v) {
    asm volatile("red.global.add.f32 [%0], %1;" :: "l"(p), "f"(v) : "memory");
}
__device__ __forceinline__ float4 ldh4(const __half* p) {
    uint2 u = *(const uint2*)p;
    float2 a = __half22float2(*(const __half2*)&u.x);
    float2 b = __half22float2(*(const __half2*)&u.y);
    return make_float4(a.x, a.y, b.x, b.y);
}

#define MMA_F16(acc, a0, a1, a2, a3, b0, b1)                                   \
    asm volatile(                                                              \
        "mma.sync.aligned.m16n8k16.row.col.f32.f16.f16.f32 "                   \
        "{%0,%1,%2,%3}, {%4,%5,%6,%7}, {%8,%9}, {%0,%1,%2,%3};"                \
        : "+f"(acc[0]), "+f"(acc[1]), "+f"(acc[2]), "+f"(acc[3])               \
        : "r"(a0), "r"(a1), "r"(a2), "r"(a3), "r"(b0), "r"(b1))

// ---------------- CSR build ----------------
__global__ void k_hist(const int* __restrict__ src, const int* __restrict__ dst,
                       int* __restrict__ cs, int* __restrict__ cd) {
    int e = blockIdx.x * 256 + threadIdx.x;
    if (e >= EE) return;
    atomicAdd(&cs[src[e]], 1);
    atomicAdd(&cd[dst[e]], 1);
}

__global__ __launch_bounds__(1024) void k_scan_block(const int* __restrict__ cnt,
                                                     int* __restrict__ excl,
                                                     int* __restrict__ bsum) {
    __shared__ int sm[1024];
    int i = blockIdx.x * 1024 + threadIdx.x;
    int v = (i < NN) ? cnt[i] : 0;
    sm[threadIdx.x] = v;
    __syncthreads();
#pragma unroll
    for (int off = 1; off < 1024; off <<= 1) {
        int t = (threadIdx.x >= off) ? sm[threadIdx.x - off] : 0;
        __syncthreads();
        sm[threadIdx.x] += t;
        __syncthreads();
    }
    if (i <= NN) excl[i] = sm[threadIdx.x] - v;
    if (threadIdx.x == 1023) bsum[blockIdx.x] = sm[1023];
}

__global__ void k_scan_tops2(int* __restrict__ b0, int* __restrict__ b1, int G) {
    if (threadIdx.x < 2) {
        int* b = threadIdx.x ? b1 : b0;
        int acc = 0;
        for (int i = 0; i < G; i++) { int t = b[i]; b[i] = acc; acc += t; }
    }
}

__global__ __launch_bounds__(1024) void k_scan_add(int* __restrict__ excl,
                                                   const int* __restrict__ bsum) {
    int i = blockIdx.x * 1024 + threadIdx.x;
    if (i <= NN) excl[i] += bsum[blockIdx.x];
}

__global__ void k_scatter(const int* __restrict__ src, const int* __restrict__ dst,
                          const int* __restrict__ rps, const int* __restrict__ rpd,
                          int* __restrict__ fills, int* __restrict__ filld,
                          int2* __restrict__ eps, int2* __restrict__ epd) {
    int e = blockIdx.x * 256 + threadIdx.x;
    if (e >= EE) return;
    int s = src[e], d = dst[e];
    int ps = rps[s] + atomicAdd(&fills[s], 1);
    eps[ps] = make_int2(d, e);
    int pd = rpd[d] + atomicAdd(&filld[d], 1);
    epd[pd] = make_int2(s, e);
}

// ---------------- GINE aggregate over dst-CSR (warp per node, no atomics) -------
__global__ __launch_bounds__(256) void k_agg_csr(
    const float* __restrict__ h, const float* __restrict__ ea,
    const int* __restrict__ rpd, const int2* __restrict__ epd,
    float* __restrict__ z, float* __restrict__ ea_out)
{
    int node = blockIdx.x * 8 + (threadIdx.x >> 5);
    if (node >= NN) return;
    int lane = threadIdx.x & 31;
    int j0 = rpd[node], j1 = rpd[node + 1];
    float4 acc = *(const float4*)(h + (size_t)node * HH + lane * 4);
    for (int j = j0; j < j1; j++) {
        int2 pr = __ldg(&epd[j]);
        float4 hv = *(const float4*)(h + (size_t)pr.x * HH + lane * 4);
        float4 ev = __ldcs((const float4*)(ea + (size_t)pr.y * HH + lane * 4));
        __stcs((float4*)(ea_out + (size_t)pr.y * HH + lane * 4), ev);
        acc.x += fmaxf(hv.x + ev.x, 0.f);
        acc.y += fmaxf(hv.y + ev.y, 0.f);
        acc.z += fmaxf(hv.z + ev.z, 0.f);
        acc.w += fmaxf(hv.w + ev.w, 0.f);
    }
    *(float4*)(z + (size_t)node * HH + lane * 4) = acc;
}

// ---------------- fused sparse attention over src-CSR (warp per node) ------------
__global__ __launch_bounds__(256) void k_attn_csr(
    const float* __restrict__ h, const __half* __restrict__ q,
    const __half* __restrict__ k, const __half* __restrict__ v,
    const int* __restrict__ rps, const int2* __restrict__ eps,
    float* __restrict__ xa, float* __restrict__ sum, float* __restrict__ sumsq)
{
    __shared__ float pbuf[8][MAXDEG_SMEM][NHH];
    __shared__ float ss[HH], sq[HH];
    if (threadIdx.x < HH) { ss[threadIdx.x] = 0.f; sq[threadIdx.x] = 0.f; }
    __syncthreads();
    int wid = threadIdx.x >> 5;
    int lane = threadIdx.x & 31;
    int node = blockIdx.x * 8 + wid;
    if (node < NN) {
        int j0 = rps[node], j1 = rps[node + 1];
        int deg = j1 - j0;
        int hd = lane >> 2, t = lane & 3;
        float4 qv = ldh4(q + (size_t)node * HH + lane * 4);
        float den = 0.f;
        for (int j = 0; j < deg; j++) {
            int2 pr = __ldg(&eps[j0 + j]);
            float4 kv = ldh4(k + (size_t)pr.x * HH + lane * 4);
            float part = qv.x * kv.x + qv.y * kv.y + qv.z * kv.z + qv.w * kv.w;
            part += __shfl_xor_sync(0xffffffffu, part, 1);
            part += __shfl_xor_sync(0xffffffffu, part, 2);
            float pe = expf(part);
            den += pe;
            if (j < MAXDEG_SMEM && t == 0) pbuf[wid][j][hd] = pe;
        }
        __syncwarp();
        float inv = (deg > 0) ? 1.f / den : 0.f;
        float4 acc = make_float4(0.f, 0.f, 0.f, 0.f);
        for (int j = 0; j < deg; j++) {
            int2 pr = __ldg(&eps[j0 + j]);
            float w;
            if (j < MAXDEG_SMEM) {
                w = pbuf[wid][j][hd] * inv;
            } else {
                float4 kv = ldh4(k + (size_t)pr.x * HH + lane * 4);
                float part = qv.x * kv.x + qv.y * kv.y + qv.z * kv.z + qv.w * kv.w;
                part += __shfl_xor_sync(0xffffffffu, part, 1);
                part += __shfl_xor_sync(0xffffffffu, part, 2);
                w = expf(part) * inv;
            }
            float4 vv = ldh4(v + (size_t)pr.x * HH + lane * 4);
            acc.x += w * vv.x; acc.y += w * vv.y;
            acc.z += w * vv.z; acc.w += w * vv.w;
        }
        float4 hv = *(const float4*)(h + (size_t)node * HH + lane * 4);
        float4 o = make_float4(hv.x + acc.x, hv.y + acc.y, hv.z + acc.z, hv.w + acc.w);
        *(float4*)(xa + (size_t)node * HH + lane * 4) = o;
        atomicAdd(&ss[lane * 4 + 0], o.x); atomicAdd(&sq[lane * 4 + 0], o.x * o.x);
        atomicAdd(&ss[lane * 4 + 1], o.y); atomicAdd(&sq[lane * 4 + 1], o.y * o.y);
        atomicAdd(&ss[lane * 4 + 2], o.z); atomicAdd(&sq[lane * 4 + 2], o.z * o.z);
        atomicAdd(&ss[lane * 4 + 3], o.w); atomicAdd(&sq[lane * 4 + 3], o.w * o.w);
    }
    __syncthreads();
    if (threadIdx.x < HH) {
        redf(&sum[threadIdx.x], ss[threadIdx.x]);
        redf(&sumsq[threadIdx.x], sq[threadIdx.x]);
    }
}

// ---------------- FP16 tensor-core GEMM (fp32 accumulate) ----------------
// C[M,Nc] = act( ((A) @ W^T + bias) * scale ); out_half -> __half C.
// Used for QKV only (structure validated in r8/r14).
__global__ __launch_bounds__(256) void k_gemm_tc(
    const float* __restrict__ A,
    const float* __restrict__ W, const float* __restrict__ bias,
    float* __restrict__ C,
    int M, int Nc, int K, float scale, int out_half)
{
    __shared__ __half2 As[128][20];
    __shared__ __half2 Bs[128][20];
    const int m0 = blockIdx.x * 128;
    const int n0 = blockIdx.y * 128;
    const int tid = threadIdx.x;
    const int wid = tid >> 5;
    const int lane = tid & 31;
    const int g = lane >> 2;
    const int t = lane & 3;
    const int wm = wid >> 1;
    const int wn = wid & 1;

    float acc[2][8][4];
#pragma unroll
    for (int mt = 0; mt < 2; mt++)
#pragma unroll
        for (int nt = 0; nt < 8; nt++)
#pragma unroll
            for (int c = 0; c < 4; c++) acc[mt][nt][c] = 0.f;

    for (int k0 = 0; k0 < K; k0 += 32) {
#pragma unroll
        for (int i = 0; i < 4; i++) {
            int idx = tid + i * 256;
            int r = idx >> 3;
            int c4 = (idx & 7) * 4;
            int ch = c4 >> 1;
            int gm = m0 + r;
            float4 va = make_float4(0.f, 0.f, 0.f, 0.f);
            if (gm < M) va = *(const float4*)(A + (size_t)gm * K + k0 + c4);
            As[r][ch + 0] = __floats2half2_rn(va.x, va.y);
            As[r][ch + 1] = __floats2half2_rn(va.z, va.w);
            float4 vb = *(const float4*)(W + (size_t)(n0 + r) * K + k0 + c4);
            Bs[r][ch + 0] = __floats2half2_rn(vb.x, vb.y);
            Bs[r][ch + 1] = __floats2half2_rn(vb.z, vb.w);
        }
        __syncthreads();

#pragma unroll
        for (int ks = 0; ks < 2; ks++) {
            const int kb = ks * 8;
            unsigned a[2][4];
#pragma unroll
            for (int mt = 0; mt < 2; mt++) {
                int r = wm * 32 + mt * 16 + g;
                a[mt][0] = *(const unsigned*)&As[r][kb + t];
                a[mt][1] = *(const unsigned*)&As[r + 8][kb + t];
                a[mt][2] = *(const unsigned*)&As[r][kb + t + 4];
                a[mt][3] = *(const unsigned*)&As[r + 8][kb + t + 4];
            }
            unsigned b[8][2];
#pragma unroll
            for (int nt = 0; nt < 8; nt++) {
                int r = wn * 64 + nt * 8 + g;
                b[nt][0] = *(const unsigned*)&Bs[r][kb + t];
                b[nt][1] = *(const unsigned*)&Bs[r][kb + t + 4];
            }
#pragma unroll
            for (int mt = 0; mt < 2; mt++)
#pragma unroll
                for (int nt = 0; nt < 8; nt++)
                    MMA_F16(acc[mt][nt], a[mt][0], a[mt][1], a[mt][2], a[mt][3],
                            b[nt][0], b[nt][1]);
        }
        __syncthreads();
    }

#pragma unroll
    for (int nt = 0; nt < 8; nt++) {
        int gn = n0 + wn * 64 + nt * 8 + 2 * t;
        float b0 = bias[gn], b1 = bias[gn + 1];
#pragma unroll
        for (int mt = 0; mt < 2; mt++) {
            int row = m0 + wm * 32 + mt * 16 + g;
            if (row < M) {
                float v0 = (acc[mt][nt][0] + b0) * scale;
                float v1 = (acc[mt][nt][1] + b1) * scale;
                if (out_half)
                    *(__half2*)((__half*)C + (size_t)row * Nc + gn) = __floats2half2_rn(v0, v1);
                else
                    *(float2*)(C + (size_t)row * Nc + gn) = make_float2(v0, v1);
            }
            int row2 = row + 8;
            if (row2 < M) {
                float v2 = (acc[mt][nt][2] + b0) * scale;
                float v3 = (acc[mt][nt][3] + b1) * scale;
                if (out_half)
                    *(__half2*)((__half*)C + (size_t)row2 * Nc + gn) = __floats2half2_rn(v2, v3);
                else
                    *(float2*)(C + (size_t)row2 * Nc + gn) = make_float2(v2, v3);
            }
        }
    }
}

// ---------------- fused 2-layer MLP: out = res + (relu(A@W1^T+b1))@W2^T+b2 -------
// A [NN,128] fp32. W1 [NCHUNK*128,128]. W2 [128, NCHUNK*128]. Hidden never leaves smem.
// Accumulates per-column BN stats of the final output.
template<int NCHUNK>
__global__ __launch_bounds__(256) void k_mlp(
    const float* __restrict__ A, const float* __restrict__ W1, const float* __restrict__ b1,
    const float* __restrict__ W2, const float* __restrict__ b2,
    const float* __restrict__ res, float* __restrict__ out,
    float* __restrict__ stat_sum, float* __restrict__ stat_sq)
{
    extern __shared__ __half2 sh[];
    __half2* As = sh;                 // [128][68]
    __half2* Bs = sh + 128 * 68;      // [128][68]
    __half2* Hs = sh + 2 * 128 * 68;  // [128][68]
    const int m0 = blockIdx.x * 128;
    const int tid = threadIdx.x;
    const int lane = tid & 31;
    const int wid = tid >> 5;
    const int g = lane >> 2, t = lane & 3;
    const int wm = wid >> 1, wn = wid & 1;
    const int K2 = NCHUNK * 128;

    // stage A once (full K = 128)
#pragma unroll
    for (int i = 0; i < 16; i++) {
        int idx = tid + i * 256;
        int r = idx >> 5;
        int c4 = (idx & 31) * 4;
        int gm = m0 + r;
        float4 va = make_float4(0.f, 0.f, 0.f, 0.f);
        if (gm < NN) va = *(const float4*)(A + (size_t)gm * 128 + c4);
        As[r * 68 + (c4 >> 1)]     = __floats2half2_rn(va.x, va.y);
        As[r * 68 + (c4 >> 1) + 1] = __floats2half2_rn(va.z, va.w);
    }

    float acc2[2][8][4];
#pragma unroll
    for (int mt = 0; mt < 2; mt++)
#pragma unroll
        for (int nt = 0; nt < 8; nt++)
#pragma unroll
            for (int c = 0; c < 4; c++) acc2[mt][nt][c] = 0.f;

#pragma unroll
    for (int hc = 0; hc < NCHUNK; hc++) {
        // stage Bs <- W1 rows [hc*128, +128), K=128
#pragma unroll
        for (int i = 0; i < 16; i++) {
            int idx = tid + i * 256;
            int r = idx >> 5;
            int c4 = (idx & 31) * 4;
            float4 vb = *(const float4*)(W1 + (size_t)(hc * 128 + r) * 128 + c4);
            Bs[r * 68 + (c4 >> 1)]     = __floats2half2_rn(vb.x, vb.y);
            Bs[r * 68 + (c4 >> 1) + 1] = __floats2half2_rn(vb.z, vb.w);
        }
        __syncthreads();

        // GEMM 1: acc1 = A @ W1c^T
        float acc1[2][8][4];
#pragma unroll
        for (int mt = 0; mt < 2; mt++)
#pragma unroll
            for (int nt = 0; nt < 8; nt++)
#pragma unroll
                for (int c = 0; c < 4; c++) acc1[mt][nt][c] = 0.f;
#pragma unroll
        for (int ks = 0; ks < 8; ks++) {
            const int kb = ks * 8;
            unsigned a[2][4];
#pragma unroll
            for (int mt = 0; mt < 2; mt++) {
                int r = wm * 32 + mt * 16 + g;
                a[mt][0] = *(const unsigned*)&As[r * 68 + kb + t];
                a[mt][1] = *(const unsigned*)&As[(r + 8) * 68 + kb + t];
                a[mt][2] = *(const unsigned*)&As[r * 68 + kb + t + 4];
                a[mt][3] = *(const unsigned*)&As[(r + 8) * 68 + kb + t + 4];
            }
            unsigned b[8][2];
#pragma unroll
            for (int nt = 0; nt < 8; nt++) {
                int r = wn * 64 + nt * 8 + g;
                b[nt][0] = *(const unsigned*)&Bs[r * 68 + kb + t];
                b[nt][1] = *(const unsigned*)&Bs[r * 68 + kb + t + 4];
            }
#pragma unroll
            for (int mt = 0; mt < 2; mt++)
#pragma unroll
                for (int nt = 0; nt < 8; nt++)
                    MMA_F16(acc1[mt][nt], a[mt][0], a[mt][1], a[mt][2], a[mt][3],
                            b[nt][0], b[nt][1]);
        }

        // hidden = relu(acc1 + b1) -> Hs in A-fragment layout (conflict-free)
#pragma unroll
        for (int nt = 0; nt < 8; nt++) {
            int gn = wn * 64 + nt * 8 + 2 * t;
            float hb0 = b1[hc * 128 + gn], hb1 = b1[hc * 128 + gn + 1];
#pragma unroll
            for (int mt = 0; mt < 2; mt++) {
                int row = wm * 32 + mt * 16 + g;
                Hs[row * 68 + (gn >> 1)] =
                    __floats2half2_rn(fmaxf(acc1[mt][nt][0] + hb0, 0.f),
                                      fmaxf(acc1[mt][nt][1] + hb1, 0.f));
                Hs[(row + 8) * 68 + (gn >> 1)] =
                    __floats2half2_rn(fmaxf(acc1[mt][nt][2] + hb0, 0.f),
                                      fmaxf(acc1[mt][nt][3] + hb1, 0.f));
            }
        }
        __syncthreads();

        // stage Bs <- W2 all 128 output rows, k cols [hc*128, +128)
#pragma unroll
        for (int i = 0; i < 16; i++) {
            int idx = tid + i * 256;
            int r = idx >> 5;
            int c4 = (idx & 31) * 4;
            float4 vb = *(const float4*)(W2 + (size_t)r * K2 + hc * 128 + c4);
            Bs[r * 68 + (c4 >> 1)]     = __floats2half2_rn(vb.x, vb.y);
            Bs[r * 68 + (c4 >> 1) + 1] = __floats2half2_rn(vb.z, vb.w);
        }
        __syncthreads();

        // GEMM 2: acc2 += hidden @ W2c^T
#pragma unroll
        for (int ks = 0; ks < 8; ks++) {
            const int kb = ks * 8;
            unsigned a[2][4];
#pragma unroll
            for (int mt = 0; mt < 2; mt++) {
                int r = wm * 32 + mt * 16 + g;
                a[mt][0] = *(const unsigned*)&Hs[r * 68 + kb + t];
                a[mt][1] = *(const unsigned*)&Hs[(r + 8) * 68 + kb + t];
                a[mt][2] = *(const unsigned*)&Hs[r * 68 + kb + t + 4];
                a[mt][3] = *(const unsigned*)&Hs[(r + 8) * 68 + kb + t + 4];
            }
            unsigned b[8][2];
#pragma unroll
            for (int nt = 0; nt < 8; nt++) {
                int r = wn * 64 + nt * 8 + g;
                b[nt][0] = *(const unsigned*)&Bs[r * 68 + kb + t];
                b[nt][1] = *(const unsigned*)&Bs[r * 68 + kb + t + 4];
            }
#pragma unroll
            for (int mt = 0; mt < 2; mt++)
#pragma unroll
                for (int nt = 0; nt < 8; nt++)
                    MMA_F16(acc2[mt][nt], a[mt][0], a[mt][1], a[mt][2], a[mt][3],
                            b[nt][0], b[nt][1]);
        }
        __syncthreads();
    }

    // epilogue: out = acc2 + b2 + res, plus column stats
#pragma unroll
    for (int nt = 0; nt < 8; nt++) {
        int gn = wn * 64 + nt * 8 + 2 * t;
        float b0 = b2[gn], b1v = b2[gn + 1];
        float cs0 = 0.f, cs1 = 0.f, cq0 = 0.f, cq1 = 0.f;
#pragma unroll
        for (int mt = 0; mt < 2; mt++) {
            int row = m0 + wm * 32 + mt * 16 + g;
            if (row < NN) {
                float2 rv = *(const float2*)(res + (size_t)row * 128 + gn);
                float v0 = acc2[mt][nt][0] + b0 + rv.x;
                float v1 = acc2[mt][nt][1] + b1v + rv.y;
                *(float2*)(out + (size_t)row * 128 + gn) = make_float2(v0, v1);
                cs0 += v0; cq0 += v0 * v0; cs1 += v1; cq1 += v1 * v1;
            }
            int row2 = row + 8;
            if (row2 < NN) {
                float2 rv = *(const float2*)(res + (size_t)row2 * 128 + gn);
                float v2 = acc2[mt][nt][2] + b0 + rv.x;
                float v3 = acc2[mt][nt][3] + b1v + rv.y;
                *(float2*)(out + (size_t)row2 * 128 + gn) = make_float2(v2, v3);
                cs0 += v2; cq0 += v2 * v2; cs1 += v3; cq1 += v3 * v3;
            }
        }
#pragma unroll
        for (int off = 4; off <= 16; off <<= 1) {
            cs0 += __shfl_xor_sync(0xffffffffu, cs0, off);
            cs1 += __shfl_xor_sync(0xffffffffu, cs1, off);
            cq0 += __shfl_xor_sync(0xffffffffu, cq0, off);
            cq1 += __shfl_xor_sync(0xffffffffu, cq1, off);
        }
        if (g == 0) {
            redf(&stat_sum[gn], cs0); redf(&stat_sum[gn + 1], cs1);
            redf(&stat_sq[gn],  cq0); redf(&stat_sq[gn + 1],  cq1);
        }
    }
}

// ---------------- BN finalize + apply ----------------
__global__ void k_bnfin01(const float* __restrict__ g0, const float* __restrict__ b0,
                          const float* __restrict__ g1, const float* __restrict__ b1) {
    int w = threadIdx.x >> 7;
    int c = threadIdx.x & 127;
    const float* g = w ? g1 : g0;
    const float* b = w ? b1 : b0;
    float mean = g_sum[w][c] * (1.f / NN);
    float var  = g_sumsq[w][c] * (1.f / NN) - mean * mean;
    float a = g[c] * rsqrtf(var + 1e-5f);
    g_bnA[w][c] = a;
    g_bnB[w][c] = b[c] - mean * a;
}

__global__ void k_bnfin(int which, const float* __restrict__ g, const float* __restrict__ b) {
    int c = threadIdx.x;
    float mean = g_sum[which][c] * (1.f / NN);
    float var  = g_sumsq[which][c] * (1.f / NN) - mean * mean;
    float a = g[c] * rsqrtf(var + 1e-5f);
    g_bnA[which][c] = a;
    g_bnB[which][c] = b[c] - mean * a;
}

__global__ void k_combine(const float* __restrict__ xl, const float* __restrict__ xa,
                          float* __restrict__ hc) {
    size_t i = (size_t)blockIdx.x * blockDim.x + threadIdx.x;
    if (i >= (size_t)NN * 32) return;
    int c4 = (int)(i & 31);
    float4 xlv = ((const float4*)xl)[i];
    float4 xav = ((const float4*)xa)[i];
    float4 a0 = *(const float4*)&g_bnA[0][c4 * 4];
    float4 b0 = *(const float4*)&g_bnB[0][c4 * 4];
    float4 a1 = *(const float4*)&g_bnA[1][c4 * 4];
    float4 b1 = *(const float4*)&g_bnB[1][c4 * 4];
    float4 o;
    o.x = a0.x * xlv.x + b0.x + a1.x * xav.x + b1.x;
    o.y = a0.y * xlv.y + b0.y + a1.y * xav.y + b1.y;
    o.z = a0.z * xlv.z + b0.z + a1.z * xav.z + b1.z;
    o.w = a0.w * xlv.w + b0.w + a1.w * xav.w + b1.w;
    ((float4*)hc)[i] = o;
}

__global__ void k_apply(const float* __restrict__ hc, float* __restrict__ out) {
    size_t i = (size_t)blockIdx.x * blockDim.x + threadIdx.x;
    if (i >= (size_t)NN * 32) return;
    int c4 = (int)(i & 31);
    float4 xv = ((const float4*)hc)[i];
    float4 a2 = *(const float4*)&g_bnA[2][c4 * 4];
    float4 b2 = *(const float4*)&g_bnB[2][c4 * 4];
    float4 o;
    o.x = a2.x * xv.x + b2.x;
    o.y = a2.y * xv.y + b2.y;
    o.z = a2.z * xv.z + b2.z;
    o.w = a2.w * xv.w + b2.w;
    ((float4*)out)[i] = o;
}

// ---------------- launcher ----------------
extern "C" void kernel_launch(void* const* d_in, const int* in_sizes, int n_in,
                              void* d_out, int out_size) {
    const float* h      = (const float*)d_in[0];
    const float* eattr  = (const float*)d_in[1];
    const int*   src    = (const int*)d_in[2];
    const int*   dst    = (const int*)d_in[3];
    const float* gin_w1 = (const float*)d_in[4];
    const float* gin_b1 = (const float*)d_in[5];
    const float* gin_w2 = (const float*)d_in[6];
    const float* gin_b2 = (const float*)d_in[7];
    const float* wq = (const float*)d_in[8];
    const float* bq = (const float*)d_in[9];
    const float* wk = (const float*)d_in[10];
    const float* bk = (const float*)d_in[11];
    const float* wv = (const float*)d_in[12];
    const float* bv = (const float*)d_in[13];
    const float* nl_g = (const float*)d_in[14];
    const float* nl_b = (const float*)d_in[15];
    const float* na_g = (const float*)d_in[16];
    const float* na_b = (const float*)d_in[17];
    const float* no_g = (const float*)d_in[18];
    const float* no_b = (const float*)d_in[19];
    const float* ffn1_w = (const float*)d_in[20];
    const float* ffn1_b = (const float*)d_in[21];
    const float* ffn2_w = (const float*)d_in[22];
    const float* ffn2_b = (const float*)d_in[23];

    float* out_hc = (float*)d_out;
    float* out_ea = (float*)d_out + (size_t)NN * HH;

    float *p_agg, *p_ao, *p_hc, *p_sum, *p_sumsq;
    __half *p_qh, *p_kh, *p_vh;
    int *p_cnt_s, *p_cnt_d, *p_fill_s, *p_fill_d, *p_rp_s, *p_rp_d, *p_bsum;
    int2 *p_eps, *p_epd;
    cudaGetSymbolAddress((void**)&p_agg,  g_agg);
    cudaGetSymbolAddress((void**)&p_qh,   g_qh);
    cudaGetSymbolAddress((void**)&p_kh,   g_kh);
    cudaGetSymbolAddress((void**)&p_vh,   g_vh);
    cudaGetSymbolAddress((void**)&p_ao,   g_ao);
    cudaGetSymbolAddress((void**)&p_hc,   g_hc);
    cudaGetSymbolAddress((void**)&p_sum,  g_sum);
    cudaGetSymbolAddress((void**)&p_sumsq, g_sumsq);
    cudaGetSymbolAddress((void**)&p_cnt_s, g_cnt_s);
    cudaGetSymbolAddress((void**)&p_cnt_d, g_cnt_d);
    cudaGetSymbolAddress((void**)&p_fill_s, g_fill_s);
    cudaGetSymbolAddress((void**)&p_fill_d, g_fill_d);
    cudaGetSymbolAddress((void**)&p_rp_s, g_rp_s);
    cudaGetSymbolAddress((void**)&p_rp_d, g_rp_d);
    cudaGetSymbolAddress((void**)&p_bsum, g_bsum);
    cudaGetSymbolAddress((void**)&p_eps, g_eps);
    cudaGetSymbolAddress((void**)&p_epd, g_epd);

    static cudaStream_t s2 = nullptr;
    static cudaEvent_t ev_fork = nullptr, ev_csr = nullptr, ev_join = nullptr;
    if (s2 == nullptr) {
        cudaStreamCreateWithFlags(&s2, cudaStreamNonBlocking);
        cudaEventCreateWithFlags(&ev_fork, cudaEventDisableTiming);
        cudaEventCreateWithFlags(&ev_csr,  cudaEventDisableTiming);
        cudaEventCreateWithFlags(&ev_join, cudaEventDisableTiming);
        cudaFuncSetAttribute(k_mlp<1>, cudaFuncAttributeMaxDynamicSharedMemorySize, MLP_SMEM);
        cudaFuncSetAttribute(k_mlp<2>, cudaFuncAttributeMaxDynamicSharedMemorySize, MLP_SMEM);
    }

    const int EB = (EE + 255) / 256;        // edge-parallel blocks
    const int NB = (NN + 7) / 8;            // warp-per-node blocks
    const int MB = (NN + 127) / 128;        // gemm row tiles
    const int SG = (NN + 1024) / 1024;      // scan blocks (covers NN+1)

    cudaMemsetAsync(p_cnt_s, 0, NN * sizeof(int));
    cudaMemsetAsync(p_cnt_d, 0, NN * sizeof(int));
    cudaMemsetAsync(p_fill_s, 0, NN * sizeof(int));
    cudaMemsetAsync(p_fill_d, 0, NN * sizeof(int));
    cudaMemsetAsync(p_sum, 0, 3 * HH * sizeof(float));
    cudaMemsetAsync(p_sumsq, 0, 3 * HH * sizeof(float));

    // fork: QKV GEMMs need only h — start immediately on s2 while main builds CSR
    cudaEventRecord(ev_fork, 0);
    cudaStreamWaitEvent(s2, ev_fork, 0);
    k_gemm_tc<<<dim3(MB, 1), 256, 0, s2>>>(h, wq, bq, (float*)p_qh, NN, HH, HH, 0.25f, 1);
    k_gemm_tc<<<dim3(MB, 1), 256, 0, s2>>>(h, wk, bk, (float*)p_kh, NN, HH, HH, 1.f, 1);
    k_gemm_tc<<<dim3(MB, 1), 256, 0, s2>>>(h, wv, bv, (float*)p_vh, NN, HH, HH, 1.f, 1);

    // main: CSR build (both directions)
    k_hist<<<EB, 256>>>(src, dst, p_cnt_s, p_cnt_d);
    k_scan_block<<<SG, 1024>>>(p_cnt_s, p_rp_s, &p_bsum[0]);
    k_scan_block<<<SG, 1024>>>(p_cnt_d, p_rp_d, &p_bsum[64]);
    k_scan_tops2<<<1, 32>>>(&p_bsum[0], &p_bsum[64], SG);
    k_scan_add<<<SG, 1024>>>(p_rp_s, &p_bsum[0]);
    k_scan_add<<<SG, 1024>>>(p_rp_d, &p_bsum[64]);
    k_scatter<<<EB, 256>>>(src, dst, p_rp_s, p_rp_d, p_fill_s, p_fill_d, p_eps, p_epd);
    cudaEventRecord(ev_csr, 0);

    // s2: fused attention (after QKV + CSR)
    cudaStreamWaitEvent(s2, ev_csr, 0);
    k_attn_csr<<<NB, 256, 0, s2>>>(h, p_qh, p_kh, p_vh, p_rp_s, p_eps,
                                   p_ao, &p_sum[1 * HH], &p_sumsq[1 * HH]);
    cudaEventRecord(ev_join, s2);

    // main: GINE aggregate (fused eattr passthrough) + fused GIN MLP
    k_agg_csr<<<NB, 256>>>(h, eattr, p_rp_d, p_epd, p_agg, out_ea);
    k_mlp<1><<<MB, 256, MLP_SMEM>>>(p_agg, gin_w1, gin_b1, gin_w2, gin_b2, h, p_agg,
                                    &p_sum[0 * HH], &p_sumsq[0 * HH]);

    // join attention branch
    cudaStreamWaitEvent(0, ev_join, 0);

    // finalize BNs 0/1, combine, fused FFN, BN2, output
    k_bnfin01<<<1, 256>>>(nl_g, nl_b, na_g, na_b);
    k_combine<<<(NN * 32 + 255) / 256, 256>>>(p_agg, p_ao, p_hc);
    k_mlp<2><<<MB, 256, MLP_SMEM>>>(p_hc, ffn1_w, ffn1_b, ffn2_w, ffn2_b, p_hc, p_hc,
                                    &p_sum[2 * HH], &p_sumsq[2 * HH]);
    k_bnfin<<<1, 128>>>(2, no_g, no_b);
    k_apply<<<(NN * 32 + 255) / 256, 256>>>(p_hc, out_hc);
}

// round 16
// speedup vs baseline: 1.1091x; 1.1091x over previous
#include <cuda_runtime.h>
#include <cuda_fp16.h>
#include <math.h>

#define NN 50000
#define EE 500000
#define HH 128
#define NHH 8
// DH = 16, scale = 0.25 (folded into q GEMM)

#define MAXDEG_SMEM 64

// ---------------- scratch (device globals; no runtime alloc) ----------------
__device__ __half g_bufh[(size_t)NN * 256];  // fp16 hidden: gin (N,128) / ffn (N,256)
__device__ float g_agg [(size_t)NN * HH];    // z = h+agg -> xl (in-place)
__device__ __half g_qh [(size_t)NN * HH];
__device__ __half g_kh [(size_t)NN * HH];
__device__ __half g_vh [(size_t)NN * HH];
__device__ float g_ao  [(size_t)NN * HH];    // xa
__device__ float g_hc  [(size_t)NN * HH];    // combine -> +FFN (in-place)
__device__ float g_sum  [3][HH];
__device__ float g_sumsq[3][HH];
__device__ float g_bnA  [3][HH];
__device__ float g_bnB  [3][HH];
// CSR scratch
__device__ int  g_cnt_s[NN];
__device__ int  g_cnt_d[NN];
__device__ int  g_fill_s[NN];
__device__ int  g_fill_d[NN];
__device__ int  g_rp_s[NN + 1];
__device__ int  g_rp_d[NN + 1];
__device__ int  g_bsum[2][64];
__device__ int2 g_eps[EE];   // (dst, eid) sorted by src
__device__ int2 g_epd[EE];   // (src, eid) sorted by dst

// ---------------- small helpers ----------------
__device__ __forceinline__ void redf(float* p, float v) {
    asm volatile("red.global.add.f32 [%0], %1;" :: "l"(p), "f"(v) : "memory");
}
__device__ __forceinline__ float4 ldh4(const __half* p) {
    uint2 u = *(const uint2*)p;
    float2 a = __half22float2(*(const __half2*)&u.x);
    float2 b = __half22float2(*(const __half2*)&u.y);
    return make_float4(a.x, a.y, b.x, b.y);
}

// ---------------- CSR build ----------------
__global__ void k_hist(const int* __restrict__ src, const int* __restrict__ dst,
                       int* __restrict__ cs, int* __restrict__ cd) {
    int e = blockIdx.x * 256 + threadIdx.x;
    if (e >= EE) return;
    atomicAdd(&cs[src[e]], 1);
    atomicAdd(&cd[dst[e]], 1);
}

__global__ __launch_bounds__(1024) void k_scan_block(const int* __restrict__ cnt,
                                                     int* __restrict__ excl,
                                                     int* __restrict__ bsum) {
    __shared__ int sm[1024];
    int i = blockIdx.x * 1024 + threadIdx.x;
    int v = (i < NN) ? cnt[i] : 0;
    sm[threadIdx.x] = v;
    __syncthreads();
#pragma unroll
    for (int off = 1; off < 1024; off <<= 1) {
        int t = (threadIdx.x >= off) ? sm[threadIdx.x - off] : 0;
        __syncthreads();
        sm[threadIdx.x] += t;
        __syncthreads();
    }
    if (i <= NN) excl[i] = sm[threadIdx.x] - v;
    if (threadIdx.x == 1023) bsum[blockIdx.x] = sm[1023];
}

__global__ void k_scan_tops2(int* __restrict__ b0, int* __restrict__ b1, int G) {
    if (threadIdx.x < 2) {
        int* b = threadIdx.x ? b1 : b0;
        int acc = 0;
        for (int i = 0; i < G; i++) { int t = b[i]; b[i] = acc; acc += t; }
    }
}

__global__ __launch_bounds__(1024) void k_scan_add(int* __restrict__ excl,
                                                   const int* __restrict__ bsum) {
    int i = blockIdx.x * 1024 + threadIdx.x;
    if (i <= NN) excl[i] += bsum[blockIdx.x];
}

__global__ void k_scatter(const int* __restrict__ src, const int* __restrict__ dst,
                          const int* __restrict__ rps, const int* __restrict__ rpd,
                          int* __restrict__ fills, int* __restrict__ filld,
                          int2* __restrict__ eps, int2* __restrict__ epd) {
    int e = blockIdx.x * 256 + threadIdx.x;
    if (e >= EE) return;
    int s = src[e], d = dst[e];
    int ps = rps[s] + atomicAdd(&fills[s], 1);
    eps[ps] = make_int2(d, e);
    int pd = rpd[d] + atomicAdd(&filld[d], 1);
    epd[pd] = make_int2(s, e);
}

// ---------------- GINE aggregate over dst-CSR (warp per node, no atomics) -------
__global__ __launch_bounds__(256) void k_agg_csr(
    const float* __restrict__ h, const float* __restrict__ ea,
    const int* __restrict__ rpd, const int2* __restrict__ epd,
    float* __restrict__ z, float* __restrict__ ea_out)
{
    int node = blockIdx.x * 8 + (threadIdx.x >> 5);
    if (node >= NN) return;
    int lane = threadIdx.x & 31;
    int j0 = rpd[node], j1 = rpd[node + 1];
    float4 acc = *(const float4*)(h + (size_t)node * HH + lane * 4);
    for (int j = j0; j < j1; j++) {
        int2 pr = __ldg(&epd[j]);
        float4 hv = *(const float4*)(h + (size_t)pr.x * HH + lane * 4);
        float4 ev = __ldcs((const float4*)(ea + (size_t)pr.y * HH + lane * 4));
        __stcs((float4*)(ea_out + (size_t)pr.y * HH + lane * 4), ev);
        acc.x += fmaxf(hv.x + ev.x, 0.f);
        acc.y += fmaxf(hv.y + ev.y, 0.f);
        acc.z += fmaxf(hv.z + ev.z, 0.f);
        acc.w += fmaxf(hv.w + ev.w, 0.f);
    }
    *(float4*)(z + (size_t)node * HH + lane * 4) = acc;
}

// ---------------- fused sparse attention over src-CSR (warp per node) ------------
// q/k/v stored as fp16 (half the gather traffic); math in fp32.
__global__ __launch_bounds__(256) void k_attn_csr(
    const float* __restrict__ h, const __half* __restrict__ q,
    const __half* __restrict__ k, const __half* __restrict__ v,
    const int* __restrict__ rps, const int2* __restrict__ eps,
    float* __restrict__ xa, float* __restrict__ sum, float* __restrict__ sumsq)
{
    __shared__ float pbuf[8][MAXDEG_SMEM][NHH];
    __shared__ float ss[HH], sq[HH];
    if (threadIdx.x < HH) { ss[threadIdx.x] = 0.f; sq[threadIdx.x] = 0.f; }
    __syncthreads();
    int wid = threadIdx.x >> 5;
    int lane = threadIdx.x & 31;
    int node = blockIdx.x * 8 + wid;
    if (node < NN) {
        int j0 = rps[node], j1 = rps[node + 1];
        int deg = j1 - j0;
        int hd = lane >> 2, t = lane & 3;
        float4 qv = ldh4(q + (size_t)node * HH + lane * 4);
        float den = 0.f;
        for (int j = 0; j < deg; j++) {
            int2 pr = __ldg(&eps[j0 + j]);
            float4 kv = ldh4(k + (size_t)pr.x * HH + lane * 4);
            float part = qv.x * kv.x + qv.y * kv.y + qv.z * kv.z + qv.w * kv.w;
            part += __shfl_xor_sync(0xffffffffu, part, 1);
            part += __shfl_xor_sync(0xffffffffu, part, 2);
            float pe = expf(part);
            den += pe;
            if (j < MAXDEG_SMEM && t == 0) pbuf[wid][j][hd] = pe;
        }
        __syncwarp();
        float inv = (deg > 0) ? 1.f / den : 0.f;
        float4 acc = make_float4(0.f, 0.f, 0.f, 0.f);
        for (int j = 0; j < deg; j++) {
            int2 pr = __ldg(&eps[j0 + j]);
            float w;
            if (j < MAXDEG_SMEM) {
                w = pbuf[wid][j][hd] * inv;
            } else {
                float4 kv = ldh4(k + (size_t)pr.x * HH + lane * 4);
                float part = qv.x * kv.x + qv.y * kv.y + qv.z * kv.z + qv.w * kv.w;
                part += __shfl_xor_sync(0xffffffffu, part, 1);
                part += __shfl_xor_sync(0xffffffffu, part, 2);
                w = expf(part) * inv;
            }
            float4 vv = ldh4(v + (size_t)pr.x * HH + lane * 4);
            acc.x += w * vv.x; acc.y += w * vv.y;
            acc.z += w * vv.z; acc.w += w * vv.w;
        }
        float4 hv = *(const float4*)(h + (size_t)node * HH + lane * 4);
        float4 o = make_float4(hv.x + acc.x, hv.y + acc.y, hv.z + acc.z, hv.w + acc.w);
        *(float4*)(xa + (size_t)node * HH + lane * 4) = o;
        atomicAdd(&ss[lane * 4 + 0], o.x); atomicAdd(&sq[lane * 4 + 0], o.x * o.x);
        atomicAdd(&ss[lane * 4 + 1], o.y); atomicAdd(&sq[lane * 4 + 1], o.y * o.y);
        atomicAdd(&ss[lane * 4 + 2], o.z); atomicAdd(&sq[lane * 4 + 2], o.z * o.z);
        atomicAdd(&ss[lane * 4 + 3], o.w); atomicAdd(&sq[lane * 4 + 3], o.w * o.w);
    }
    __syncthreads();
    if (threadIdx.x < HH) {
        redf(&sum[threadIdx.x], ss[threadIdx.x]);
        redf(&sumsq[threadIdx.x], sq[threadIdx.x]);
    }
}

// ---------------- FP16 tensor-core GEMM (fp32 accumulate) ----------------
// C[M,Nc] = act( ((A) @ W^T + bias) * scale ) [+res], optional fused column stats.
// AHALF (compile-time): A is __half — staging is a pure copy, no conversion.
// out_half (runtime, epilogue only): write C as __half.
template<int AHALF>
__global__ __launch_bounds__(256) void k_gemm_tc(
    const void* __restrict__ Av,
    const float* __restrict__ W, const float* __restrict__ bias,
    const float* __restrict__ res, float* __restrict__ C,
    int M, int Nc, int K, float scale, int do_relu, int out_half,
    float* __restrict__ stat_sum, float* __restrict__ stat_sq)
{
    __shared__ __half2 As[128][20];
    __shared__ __half2 Bs[128][20];
    const int m0 = blockIdx.x * 128;
    const int n0 = blockIdx.y * 128;
    const int tid = threadIdx.x;
    const int wid = tid >> 5;
    const int lane = tid & 31;
    const int g = lane >> 2;
    const int t = lane & 3;
    const int wm = wid >> 1;
    const int wn = wid & 1;

    float acc[2][8][4];
#pragma unroll
    for (int mt = 0; mt < 2; mt++)
#pragma unroll
        for (int nt = 0; nt < 8; nt++)
#pragma unroll
            for (int c = 0; c < 4; c++) acc[mt][nt][c] = 0.f;

    for (int k0 = 0; k0 < K; k0 += 32) {
#pragma unroll
        for (int i = 0; i < 4; i++) {
            int idx = tid + i * 256;
            int r = idx >> 3;
            int c4 = (idx & 7) * 4;
            int ch = c4 >> 1;
            int gm = m0 + r;
            if (AHALF) {
                uint2 ua = make_uint2(0u, 0u);
                if (gm < M)
                    ua = *(const uint2*)((const __half*)Av + (size_t)gm * K + k0 + c4);
                As[r][ch + 0] = *(const __half2*)&ua.x;
                As[r][ch + 1] = *(const __half2*)&ua.y;
            } else {
                float4 va = make_float4(0.f, 0.f, 0.f, 0.f);
                if (gm < M)
                    va = *(const float4*)((const float*)Av + (size_t)gm * K + k0 + c4);
                As[r][ch + 0] = __floats2half2_rn(va.x, va.y);
                As[r][ch + 1] = __floats2half2_rn(va.z, va.w);
            }
            float4 vb = *(const float4*)(W + (size_t)(n0 + r) * K + k0 + c4);
            Bs[r][ch + 0] = __floats2half2_rn(vb.x, vb.y);
            Bs[r][ch + 1] = __floats2half2_rn(vb.z, vb.w);
        }
        __syncthreads();

#pragma unroll
        for (int ks = 0; ks < 2; ks++) {
            const int kb = ks * 8;
            unsigned a[2][4];
#pragma unroll
            for (int mt = 0; mt < 2; mt++) {
                int r = wm * 32 + mt * 16 + g;
                a[mt][0] = *(const unsigned*)&As[r][kb + t];
                a[mt][1] = *(const unsigned*)&As[r + 8][kb + t];
                a[mt][2] = *(const unsigned*)&As[r][kb + t + 4];
                a[mt][3] = *(const unsigned*)&As[r + 8][kb + t + 4];
            }
            unsigned b[8][2];
#pragma unroll
            for (int nt = 0; nt < 8; nt++) {
                int r = wn * 64 + nt * 8 + g;
                b[nt][0] = *(const unsigned*)&Bs[r][kb + t];
                b[nt][1] = *(const unsigned*)&Bs[r][kb + t + 4];
            }
#pragma unroll
            for (int mt = 0; mt < 2; mt++)
#pragma unroll
                for (int nt = 0; nt < 8; nt++) {
                    asm volatile(
                        "mma.sync.aligned.m16n8k16.row.col.f32.f16.f16.f32 "
                        "{%0,%1,%2,%3}, {%4,%5,%6,%7}, {%8,%9}, {%0,%1,%2,%3};"
                        : "+f"(acc[mt][nt][0]), "+f"(acc[mt][nt][1]),
                          "+f"(acc[mt][nt][2]), "+f"(acc[mt][nt][3])
                        : "r"(a[mt][0]), "r"(a[mt][1]), "r"(a[mt][2]), "r"(a[mt][3]),
                          "r"(b[nt][0]), "r"(b[nt][1]));
                }
        }
        __syncthreads();
    }

#pragma unroll
    for (int nt = 0; nt < 8; nt++) {
        int gn = n0 + wn * 64 + nt * 8 + 2 * t;
        float b0 = bias[gn], b1 = bias[gn + 1];
        float cs0 = 0.f, cs1 = 0.f, cq0 = 0.f, cq1 = 0.f;
#pragma unroll
        for (int mt = 0; mt < 2; mt++) {
            int row = m0 + wm * 32 + mt * 16 + g;
            if (row < M) {
                float v0 = (acc[mt][nt][0] + b0) * scale;
                float v1 = (acc[mt][nt][1] + b1) * scale;
                if (do_relu) { v0 = fmaxf(v0, 0.f); v1 = fmaxf(v1, 0.f); }
                if (res) {
                    float2 rv = *(const float2*)(res + (size_t)row * Nc + gn);
                    v0 += rv.x; v1 += rv.y;
                }
                if (out_half)
                    *(__half2*)((__half*)C + (size_t)row * Nc + gn) = __floats2half2_rn(v0, v1);
                else
                    *(float2*)(C + (size_t)row * Nc + gn) = make_float2(v0, v1);
                cs0 += v0; cq0 += v0 * v0; cs1 += v1; cq1 += v1 * v1;
            }
            int row2 = row + 8;
            if (row2 < M) {
                float v2 = (acc[mt][nt][2] + b0) * scale;
                float v3 = (acc[mt][nt][3] + b1) * scale;
                if (do_relu) { v2 = fmaxf(v2, 0.f); v3 = fmaxf(v3, 0.f); }
                if (res) {
                    float2 rv = *(const float2*)(res + (size_t)row2 * Nc + gn);
                    v2 += rv.x; v3 += rv.y;
                }
                if (out_half)
                    *(__half2*)((__half*)C + (size_t)row2 * Nc + gn) = __floats2half2_rn(v2, v3);
                else
                    *(float2*)(C + (size_t)row2 * Nc + gn) = make_float2(v2, v3);
                cs0 += v2; cq0 += v2 * v2; cs1 += v3; cq1 += v3 * v3;
            }
        }
        if (stat_sum) {
#pragma unroll
            for (int off = 4; off <= 16; off <<= 1) {
                cs0 += __shfl_xor_sync(0xffffffffu, cs0, off);
                cs1 += __shfl_xor_sync(0xffffffffu, cs1, off);
                cq0 += __shfl_xor_sync(0xffffffffu, cq0, off);
                cq1 += __shfl_xor_sync(0xffffffffu, cq1, off);
            }
            if (g == 0) {
                redf(&stat_sum[gn], cs0); redf(&stat_sum[gn + 1], cs1);
                redf(&stat_sq[gn],  cq0); redf(&stat_sq[gn + 1],  cq1);
            }
        }
    }
}

// ---------------- BN finalize + apply ----------------
__global__ void k_bnfin01(const float* __restrict__ g0, const float* __restrict__ b0,
                          const float* __restrict__ g1, const float* __restrict__ b1) {
    int w = threadIdx.x >> 7;
    int c = threadIdx.x & 127;
    const float* g = w ? g1 : g0;
    const float* b = w ? b1 : b0;
    float mean = g_sum[w][c] * (1.f / NN);
    float var  = g_sumsq[w][c] * (1.f / NN) - mean * mean;
    float a = g[c] * rsqrtf(var + 1e-5f);
    g_bnA[w][c] = a;
    g_bnB[w][c] = b[c] - mean * a;
}

__global__ void k_bnfin(int which, const float* __restrict__ g, const float* __restrict__ b) {
    int c = threadIdx.x;
    float mean = g_sum[which][c] * (1.f / NN);
    float var  = g_sumsq[which][c] * (1.f / NN) - mean * mean;
    float a = g[c] * rsqrtf(var + 1e-5f);
    g_bnA[which][c] = a;
    g_bnB[which][c] = b[c] - mean * a;
}

__global__ void k_combine(const float* __restrict__ xl, const float* __restrict__ xa,
                          float* __restrict__ hc) {
    size_t i = (size_t)blockIdx.x * blockDim.x + threadIdx.x;
    if (i >= (size_t)NN * 32) return;
    int c4 = (int)(i & 31);
    float4 xlv = ((const float4*)xl)[i];
    float4 xav = ((const float4*)xa)[i];
    float4 a0 = *(const float4*)&g_bnA[0][c4 * 4];
    float4 b0 = *(const float4*)&g_bnB[0][c4 * 4];
    float4 a1 = *(const float4*)&g_bnA[1][c4 * 4];
    float4 b1 = *(const float4*)&g_bnB[1][c4 * 4];
    float4 o;
    o.x = a0.x * xlv.x + b0.x + a1.x * xav.x + b1.x;
    o.y = a0.y * xlv.y + b0.y + a1.y * xav.y + b1.y;
    o.z = a0.z * xlv.z + b0.z + a1.z * xav.z + b1.z;
    o.w = a0.w * xlv.w + b0.w + a1.w * xav.w + b1.w;
    ((float4*)hc)[i] = o;
}

__global__ void k_apply(const float* __restrict__ hc, float* __restrict__ out) {
    size_t i = (size_t)blockIdx.x * blockDim.x + threadIdx.x;
    if (i >= (size_t)NN * 32) return;
    int c4 = (int)(i & 31);
    float4 xv = ((const float4*)hc)[i];
    float4 a2 = *(const float4*)&g_bnA[2][c4 * 4];
    float4 b2 = *(const float4*)&g_bnB[2][c4 * 4];
    float4 o;
    o.x = a2.x * xv.x + b2.x;
    o.y = a2.y * xv.y + b2.y;
    o.z = a2.z * xv.z + b2.z;
    o.w = a2.w * xv.w + b2.w;
    ((float4*)out)[i] = o;
}

// ---------------- launcher ----------------
extern "C" void kernel_launch(void* const* d_in, const int* in_sizes, int n_in,
                              void* d_out, int out_size) {
    const float* h      = (const float*)d_in[0];
    const float* eattr  = (const float*)d_in[1];
    const int*   src    = (const int*)d_in[2];
    const int*   dst    = (const int*)d_in[3];
    const float* gin_w1 = (const float*)d_in[4];
    const float* gin_b1 = (const float*)d_in[5];
    const float* gin_w2 = (const float*)d_in[6];
    const float* gin_b2 = (const float*)d_in[7];
    const float* wq = (const float*)d_in[8];
    const float* bq = (const float*)d_in[9];
    const float* wk = (const float*)d_in[10];
    const float* bk = (const float*)d_in[11];
    const float* wv = (const float*)d_in[12];
    const float* bv = (const float*)d_in[13];
    const float* nl_g = (const float*)d_in[14];
    const float* nl_b = (const float*)d_in[15];
    const float* na_g = (const float*)d_in[16];
    const float* na_b = (const float*)d_in[17];
    const float* no_g = (const float*)d_in[18];
    const float* no_b = (const float*)d_in[19];
    const float* ffn1_w = (const float*)d_in[20];
    const float* ffn1_b = (const float*)d_in[21];
    const float* ffn2_w = (const float*)d_in[22];
    const float* ffn2_b = (const float*)d_in[23];

    float* out_hc = (float*)d_out;
    float* out_ea = (float*)d_out + (size_t)NN * HH;

    float *p_agg, *p_ao, *p_hc, *p_sum, *p_sumsq;
    __half *p_qh, *p_kh, *p_vh, *p_bufh;
    int *p_cnt_s, *p_cnt_d, *p_fill_s, *p_fill_d, *p_rp_s, *p_rp_d, *p_bsum;
    int2 *p_eps, *p_epd;
    cudaGetSymbolAddress((void**)&p_bufh, g_bufh);
    cudaGetSymbolAddress((void**)&p_agg,  g_agg);
    cudaGetSymbolAddress((void**)&p_qh,   g_qh);
    cudaGetSymbolAddress((void**)&p_kh,   g_kh);
    cudaGetSymbolAddress((void**)&p_vh,   g_vh);
    cudaGetSymbolAddress((void**)&p_ao,   g_ao);
    cudaGetSymbolAddress((void**)&p_hc,   g_hc);
    cudaGetSymbolAddress((void**)&p_sum,  g_sum);
    cudaGetSymbolAddress((void**)&p_sumsq, g_sumsq);
    cudaGetSymbolAddress((void**)&p_cnt_s, g_cnt_s);
    cudaGetSymbolAddress((void**)&p_cnt_d, g_cnt_d);
    cudaGetSymbolAddress((void**)&p_fill_s, g_fill_s);
    cudaGetSymbolAddress((void**)&p_fill_d, g_fill_d);
    cudaGetSymbolAddress((void**)&p_rp_s, g_rp_s);
    cudaGetSymbolAddress((void**)&p_rp_d, g_rp_d);
    cudaGetSymbolAddress((void**)&p_bsum, g_bsum);
    cudaGetSymbolAddress((void**)&p_eps, g_eps);
    cudaGetSymbolAddress((void**)&p_epd, g_epd);

    static cudaStream_t s2 = nullptr;
    static cudaEvent_t ev_fork = nullptr, ev_csr = nullptr, ev_join = nullptr;
    if (s2 == nullptr) {
        cudaStreamCreateWithFlags(&s2, cudaStreamNonBlocking);
        cudaEventCreateWithFlags(&ev_fork, cudaEventDisableTiming);
        cudaEventCreateWithFlags(&ev_csr,  cudaEventDisableTiming);
        cudaEventCreateWithFlags(&ev_join, cudaEventDisableTiming);
    }

    const int EB = (EE + 255) / 256;        // edge-parallel blocks
    const int NB = (NN + 7) / 8;            // warp-per-node blocks
    const int MB = (NN + 127) / 128;        // gemm row tiles
    const int SG = (NN + 1024) / 1024;      // scan blocks (covers NN+1)

    cudaMemsetAsync(p_cnt_s, 0, NN * sizeof(int));
    cudaMemsetAsync(p_cnt_d, 0, NN * sizeof(int));
    cudaMemsetAsync(p_fill_s, 0, NN * sizeof(int));
    cudaMemsetAsync(p_fill_d, 0, NN * sizeof(int));
    cudaMemsetAsync(p_sum, 0, 3 * HH * sizeof(float));
    cudaMemsetAsync(p_sumsq, 0, 3 * HH * sizeof(float));

    // fork: QKV GEMMs need only h — start immediately on s2 while main builds CSR
    cudaEventRecord(ev_fork, 0);
    cudaStreamWaitEvent(s2, ev_fork, 0);
    k_gemm_tc<0><<<dim3(MB, 1), 256, 0, s2>>>(h, wq, bq, nullptr, (float*)p_qh,
                                              NN, HH, HH, 0.25f, 0, 1, nullptr, nullptr);
    k_gemm_tc<0><<<dim3(MB, 1), 256, 0, s2>>>(h, wk, bk, nullptr, (float*)p_kh,
                                              NN, HH, HH, 1.f, 0, 1, nullptr, nullptr);
    k_gemm_tc<0><<<dim3(MB, 1), 256, 0, s2>>>(h, wv, bv, nullptr, (float*)p_vh,
                                              NN, HH, HH, 1.f, 0, 1, nullptr, nullptr);

    // main: CSR build (both directions)
    k_hist<<<EB, 256>>>(src, dst, p_cnt_s, p_cnt_d);
    k_scan_block<<<SG, 1024>>>(p_cnt_s, p_rp_s, &p_bsum[0]);
    k_scan_block<<<SG, 1024>>>(p_cnt_d, p_rp_d, &p_bsum[64]);
    k_scan_tops2<<<1, 32>>>(&p_bsum[0], &p_bsum[64], SG);
    k_scan_add<<<SG, 1024>>>(p_rp_s, &p_bsum[0]);
    k_scan_add<<<SG, 1024>>>(p_rp_d, &p_bsum[64]);
    k_scatter<<<EB, 256>>>(src, dst, p_rp_s, p_rp_d, p_fill_s, p_fill_d, p_eps, p_epd);
    cudaEventRecord(ev_csr, 0);

    // s2: fused attention (after QKV + CSR)
    cudaStreamWaitEvent(s2, ev_csr, 0);
    k_attn_csr<<<NB, 256, 0, s2>>>(h, p_qh, p_kh, p_vh, p_rp_s, p_eps,
                                   p_ao, &p_sum[1 * HH], &p_sumsq[1 * HH]);
    cudaEventRecord(ev_join, s2);

    // main: GINE aggregate (fused eattr passthrough) + GIN MLP (fp16 hidden)
    k_agg_csr<<<NB, 256>>>(h, eattr, p_rp_d, p_epd, p_agg, out_ea);
    k_gemm_tc<0><<<dim3(MB, 1), 256>>>(p_agg, gin_w1, gin_b1, nullptr, (float*)p_bufh,
                                       NN, HH, HH, 1.f, 1, 1, nullptr, nullptr);
    k_gemm_tc<1><<<dim3(MB, 1), 256>>>(p_bufh, gin_w2, gin_b2, h, p_agg,
                                       NN, HH, HH, 1.f, 0, 0, &p_sum[0 * HH], &p_sumsq[0 * HH]);

    // join attention branch
    cudaStreamWaitEvent(0, ev_join, 0);

    // finalize BNs 0/1, combine, FFN (fp16 hidden), BN2, output
    k_bnfin01<<<1, 256>>>(nl_g, nl_b, na_g, na_b);
    k_combine<<<(NN * 32 + 255) / 256, 256>>>(p_agg, p_ao, p_hc);
    k_gemm_tc<0><<<dim3(MB, 2), 256>>>(p_hc, ffn1_w, ffn1_b, nullptr, (float*)p_bufh,
                                       NN, 256, HH, 1.f, 1, 1, nullptr, nullptr);
    k_gemm_tc<1><<<dim3(MB, 1), 256>>>(p_bufh, ffn2_w, ffn2_b, p_hc, p_hc,
                                       NN, HH, 256, 1.f, 0, 0, &p_sum[2 * HH], &p_sumsq[2 * HH]);
    k_bnfin<<<1, 128>>>(2, no_g, no_b);
    k_apply<<<(NN * 32 + 255) / 256, 256>>>(p_hc, out_hc);
}